// round 2
// baseline (speedup 1.0000x reference)
#include <cuda_runtime.h>

#define MAXN 50000
#define HCH  128

// ---------------- scratch (static device globals; no runtime allocation) ----------------
__device__ float g_hL[(size_t)MAXN * HCH];
__device__ float g_hG[(size_t)MAXN * HCH];
__device__ float g_aL[(size_t)MAXN * HCH];
__device__ float g_aG[(size_t)MAXN * HCH];
__device__ float g_xA[(size_t)MAXN * HCH];
__device__ float g_xB[(size_t)MAXN * HCH];
__device__ float g_iL[MAXN];
__device__ float g_iG[MAXN];
__device__ int   g_dL[MAXN];
__device__ int   g_dG[MAXN];

// ---------------- f32x2 helpers ----------------
typedef unsigned long long u64;

__device__ __forceinline__ u64 pk2(float lo, float hi) {
    u64 r; asm("mov.b64 %0, {%1, %2};" : "=l"(r) : "f"(lo), "f"(hi)); return r;
}
__device__ __forceinline__ u64 fma2(u64 a, u64 b, u64 c) {
    u64 d; asm("fma.rn.f32x2 %0, %1, %2, %3;" : "=l"(d) : "l"(a), "l"(b), "l"(c)); return d;
}
__device__ __forceinline__ u64 add2(u64 a, u64 b) {
    u64 d; asm("add.rn.f32x2 %0, %1, %2;" : "=l"(d) : "l"(a), "l"(b)); return d;
}
__device__ __forceinline__ u64 mul2(u64 a, u64 b) {
    u64 d; asm("mul.rn.f32x2 %0, %1, %2;" : "=l"(d) : "l"(a), "l"(b)); return d;
}

// ---------------- degree / dinv ----------------
__global__ void k_degzero(int* dL, int* dG, int n) {
    int i = blockIdx.x * blockDim.x + threadIdx.x;
    if (i < n) { dL[i] = 0; dG[i] = 0; }
}
__global__ void k_count(const int* __restrict__ dst, int E, int* __restrict__ deg) {
    int e = blockIdx.x * blockDim.x + threadIdx.x;
    if (e < E) atomicAdd(&deg[dst[e]], 1);
}
__global__ void k_dinv(const int* __restrict__ dL, const int* __restrict__ dG,
                       float* __restrict__ iL, float* __restrict__ iG, int n) {
    int i = blockIdx.x * blockDim.x + threadIdx.x;
    if (i < n) {
        iL[i] = rsqrtf((float)dL[i] + 2.0f);
        iG[i] = rsqrtf((float)dG[i] + 2.0f);
    }
}

// ---------------- SGEMM: C[M x 128] = A[M x 128] @ B[128 x 128], f32x2 inner ----------------
// rowscale != nullptr: C[row,:] *= rowscale[row]  (used to pre-fold dinv[src] into h)
// bias     != nullptr: += bias[col]
// Cin      != nullptr: += Cin[row,col]   (Cin may alias C)
__global__ __launch_bounds__(128) void sgemm_k128(
    const float* __restrict__ A, const float* __restrict__ B,
    const float* __restrict__ bias, const float* __restrict__ rowscale,
    const float* Cin, float* C, int M)
{
    __shared__ float As[8][64];
    __shared__ float Bs[8][128];
    const int t   = threadIdx.x;
    const int tx  = t & 15;   // column group: pairs at tx*2 + j*32
    const int ty  = t >> 4;   // row group: rows ty*8 .. ty*8+7
    const int row0 = blockIdx.x * 64;

    u64 acc[8][4];
#pragma unroll
    for (int i = 0; i < 8; i++)
#pragma unroll
        for (int j = 0; j < 4; j++) acc[i][j] = 0ull;

    const int ar = t >> 1;          // 0..63
    const int ak = (t & 1) * 4;     // 0 or 4
    const int bk = t >> 4;          // 0..7
    const int bc = (t & 15) * 8;    // 0..120
    const bool avalid = (row0 + ar) < M;
    const float* Aptr = A + (size_t)(row0 + ar) * 128 + ak;

    for (int k0 = 0; k0 < 128; k0 += 8) {
        float4 av = avalid ? *(const float4*)(Aptr + k0) : make_float4(0.f, 0.f, 0.f, 0.f);
        float4 bv0 = *(const float4*)(B + (size_t)(k0 + bk) * 128 + bc);
        float4 bv1 = *(const float4*)(B + (size_t)(k0 + bk) * 128 + bc + 4);
        __syncthreads();
        As[ak + 0][ar] = av.x; As[ak + 1][ar] = av.y;
        As[ak + 2][ar] = av.z; As[ak + 3][ar] = av.w;
        *(float4*)&Bs[bk][bc]     = bv0;
        *(float4*)&Bs[bk][bc + 4] = bv1;
        __syncthreads();
#pragma unroll
        for (int kk = 0; kk < 8; kk++) {
            float4 a0 = *(const float4*)&As[kk][ty * 8];
            float4 a1 = *(const float4*)&As[kk][ty * 8 + 4];
            u64 b0 = *(const u64*)&Bs[kk][tx * 2];
            u64 b1 = *(const u64*)&Bs[kk][tx * 2 + 32];
            u64 b2 = *(const u64*)&Bs[kk][tx * 2 + 64];
            u64 b3 = *(const u64*)&Bs[kk][tx * 2 + 96];
            u64 ad[8] = { pk2(a0.x, a0.x), pk2(a0.y, a0.y), pk2(a0.z, a0.z), pk2(a0.w, a0.w),
                          pk2(a1.x, a1.x), pk2(a1.y, a1.y), pk2(a1.z, a1.z), pk2(a1.w, a1.w) };
#pragma unroll
            for (int i = 0; i < 8; i++) {
                acc[i][0] = fma2(ad[i], b0, acc[i][0]);
                acc[i][1] = fma2(ad[i], b1, acc[i][1]);
                acc[i][2] = fma2(ad[i], b2, acc[i][2]);
                acc[i][3] = fma2(ad[i], b3, acc[i][3]);
            }
        }
    }

#pragma unroll
    for (int i = 0; i < 8; i++) {
        int row = row0 + ty * 8 + i;
        if (row >= M) continue;
        size_t rbase = (size_t)row * 128;
        u64 sc = 0ull;
        if (rowscale) { float s = rowscale[row]; sc = pk2(s, s); }
#pragma unroll
        for (int j = 0; j < 4; j++) {
            int c = tx * 2 + j * 32;
            u64 v = acc[i][j];
            if (rowscale) v = mul2(v, sc);
            if (bias)     v = add2(v, *(const u64*)(bias + c));
            if (Cin)      v = add2(v, *(const u64*)(Cin + rbase + c));
            *(u64*)(C + rbase + c) = v;
        }
    }
}

// ---------------- self-loop init: agg = hs*2*dinv + b ----------------
__global__ __launch_bounds__(256) void k_selfinit(
    const float* __restrict__ hL, const float* __restrict__ hG,
    const float* __restrict__ iL, const float* __restrict__ iG,
    const float* __restrict__ bL, const float* __restrict__ bG,
    float* __restrict__ aL, float* __restrict__ aG, int n)
{
    int i = blockIdx.x * blockDim.x + threadIdx.x;
    if (i >= n * 32) return;
    int row = i >> 5;
    int c4  = (i & 31) * 4;
    size_t off = (size_t)row * 128 + c4;
    float sL = 2.0f * iL[row];
    float sG = 2.0f * iG[row];
    float4 h = *(const float4*)(hL + off);
    float4 b = *(const float4*)(bL + c4);
    float4 o;
    o.x = h.x * sL + b.x; o.y = h.y * sL + b.y; o.z = h.z * sL + b.z; o.w = h.w * sL + b.w;
    *(float4*)(aL + off) = o;
    h = *(const float4*)(hG + off);
    b = *(const float4*)(bG + c4);
    o.x = h.x * sG + b.x; o.y = h.y * sG + b.y; o.z = h.z * sG + b.z; o.w = h.w * sG + b.w;
    *(float4*)(aG + off) = o;
}

// ---------------- edge scatter-add: agg[dst] += hs[src] * dinv[dst] ----------------
__global__ __launch_bounds__(256) void k_edge(
    const float* __restrict__ hs, const float* __restrict__ dinv,
    const int* __restrict__ src, const int* __restrict__ dst,
    float* __restrict__ agg, int E)
{
    int w = (int)((blockIdx.x * 256u + threadIdx.x) >> 5);
    if (w >= E) return;
    int lane = threadIdx.x & 31;
    int s = __ldg(src + w);
    int d = __ldg(dst + w);
    float c = __ldg(dinv + d);
    float4 v = *(const float4*)(hs + (size_t)s * 128 + lane * 4);
    float* p = agg + (size_t)d * 128 + lane * 4;
    asm volatile("red.global.add.v4.f32 [%0], {%1, %2, %3, %4};"
                 :: "l"(p), "f"(v.x * c), "f"(v.y * c), "f"(v.z * c), "f"(v.w * c)
                 : "memory");
}

// ---------------- LayerNorm + ReLU (+ optional residual), in place ----------------
__global__ __launch_bounds__(256) void k_ln(
    float* __restrict__ a, const float* __restrict__ g, const float* __restrict__ b,
    const float* __restrict__ res, int n)
{
    int w = (int)((blockIdx.x * 256u + threadIdx.x) >> 5);
    if (w >= n) return;
    int lane = threadIdx.x & 31;
    size_t off = (size_t)w * 128 + lane * 4;
    float4 v = *(const float4*)(a + off);
    float s = v.x + v.y + v.z + v.w;
#pragma unroll
    for (int o = 16; o; o >>= 1) s += __shfl_xor_sync(0xffffffffu, s, o);
    float mu = s * (1.0f / 128.0f);
    float4 xc = make_float4(v.x - mu, v.y - mu, v.z - mu, v.w - mu);
    float q = xc.x * xc.x + xc.y * xc.y + xc.z * xc.z + xc.w * xc.w;
#pragma unroll
    for (int o = 16; o; o >>= 1) q += __shfl_xor_sync(0xffffffffu, q, o);
    float r = rsqrtf(q * (1.0f / 128.0f) + 1e-5f);
    float4 g4 = *(const float4*)(g + lane * 4);
    float4 b4 = *(const float4*)(b + lane * 4);
    float4 o4;
    o4.x = fmaxf(xc.x * r * g4.x + b4.x, 0.0f);
    o4.y = fmaxf(xc.y * r * g4.y + b4.y, 0.0f);
    o4.z = fmaxf(xc.z * r * g4.z + b4.z, 0.0f);
    o4.w = fmaxf(xc.w * r * g4.w + b4.w, 0.0f);
    if (res) {
        float4 rv = *(const float4*)(res + off);
        o4.x += rv.x; o4.y += rv.y; o4.z += rv.z; o4.w += rv.w;
    }
    *(float4*)(a + off) = o4;
}

// ---------------- final: proj = x @ finW + finb (N x 64), plus passthrough copy of x ----------------
__global__ __launch_bounds__(256) void k_final(
    const float* __restrict__ x, const float* __restrict__ W,
    const float* __restrict__ bias, float* proj, float* xdst,
    int n, int do_proj, int do_copy)
{
    __shared__ float Ws[128 * 64];
    __shared__ float xs[16 * 128];
    int t = threadIdx.x;
    if (do_proj) {
        for (int i = t; i < 128 * 64; i += 256) Ws[i] = W[i];
    }
    int row0 = blockIdx.x * 16;
    for (int i = t; i < 16 * 32; i += 256) {
        int r  = i >> 5;
        int c4 = (i & 31) * 4;
        int row = row0 + r;
        float4 v = (row < n) ? *(const float4*)(x + (size_t)row * 128 + c4)
                             : make_float4(0.f, 0.f, 0.f, 0.f);
        *(float4*)&xs[r * 128 + c4] = v;
    }
    __syncthreads();
    if (do_proj) {
        int c = t & 63;
        for (int rp = 0; rp < 4; rp++) {
            int rl = rp * 4 + (t >> 6);
            int row = row0 + rl;
            if (row < n) {
                float acc = 0.0f;
#pragma unroll
                for (int k = 0; k < 128; k++) acc = fmaf(xs[rl * 128 + k], Ws[k * 64 + c], acc);
                proj[(size_t)row * 64 + c] = acc + bias[c];
            }
        }
    }
    if (do_copy) {
        for (int i = t; i < 16 * 32; i += 256) {
            int r  = i >> 5;
            int c4 = (i & 31) * 4;
            int row = row0 + r;
            if (row < n)
                *(float4*)(xdst + (size_t)row * 128 + c4) = *(const float4*)&xs[r * 128 + c4];
        }
    }
}

// ---------------- host ----------------
static float* symF(const void* sym) { void* p = nullptr; cudaGetSymbolAddress(&p, sym); return (float*)p; }
static int*   symI(const void* sym) { void* p = nullptr; cudaGetSymbolAddress(&p, sym); return (int*)p; }

extern "C" void kernel_launch(void* const* d_in, const int* in_sizes, int n_in,
                              void* d_out, int out_size)
{
    const float* x    = (const float*)d_in[0];
    const float* WL   = (const float*)d_in[1];
    const float* bL   = (const float*)d_in[2];
    const float* WG   = (const float*)d_in[3];
    const float* bG   = (const float*)d_in[4];
    const float* linW = (const float*)d_in[5];
    const float* linb = (const float*)d_in[6];
    const float* ln_g = (const float*)d_in[7];
    const float* ln_b = (const float*)d_in[8];
    const float* finW = (const float*)d_in[9];
    const float* finb = (const float*)d_in[10];
    const int*   Gei  = (const int*)d_in[11];
    const int*   Lei  = (const int*)d_in[12];

    int n  = in_sizes[0] / HCH;
    if (n > MAXN) n = MAXN;
    int EG = in_sizes[11] / 2;
    int EL = in_sizes[12] / 2;
    const int *Gsrc = Gei, *Gdst = Gei + EG;
    const int *Lsrc = Lei, *Ldst = Lei + EL;

    float* hL = symF(g_hL); float* hG = symF(g_hG);
    float* aL = symF(g_aL); float* aG = symF(g_aG);
    float* xA = symF(g_xA); float* xB = symF(g_xB);
    float* iL = symF(g_iL); float* iG = symF(g_iG);
    int*   dL = symI(g_dL); int*   dG = symI(g_dG);

    const int TB = 256;
    int gbN   = (n + TB - 1) / TB;
    int gbN32 = (n * 32 + TB - 1) / TB;
    int gbGem = (n + 63) / 64;

    // degrees + dinv (edge sets are inputs; recomputed every call — deterministic)
    k_degzero<<<gbN, TB>>>(dL, dG, n);
    k_count<<<(EL + TB - 1) / TB, TB>>>(Ldst, EL, dL);
    k_count<<<(EG + TB - 1) / TB, TB>>>(Gdst, EG, dG);
    k_dinv<<<gbN, TB>>>(dL, dG, iL, iG, n);

    const float* xin = x;
    float* xout = xA;
    for (int i = 0; i < 3; i++) {
        const float* WLi = WL + (size_t)i * 128 * 128;
        const float* WGi = WG + (size_t)i * 128 * 128;
        const float* bLi = bL + i * 128;
        const float* bGi = bG + i * 128;
        const float* lwT = linW + (size_t)i * 256 * 128;          // rows 0..127  (xG part)
        const float* lwB = lwT + 128 * 128;                        // rows 128..255 (xL part)
        const float* lbi = linb + i * 128;

        // hs = (x @ W) * dinv[row]   (dinv[src] pre-folded)
        sgemm_k128<<<gbGem, 128>>>(xin, WLi, nullptr, iL, nullptr, hL, n);
        sgemm_k128<<<gbGem, 128>>>(xin, WGi, nullptr, iG, nullptr, hG, n);
        // agg = hs*2*dinv + bias
        k_selfinit<<<gbN32, TB>>>(hL, hG, iL, iG, bLi, bGi, aL, aG, n);
        // agg[dst] += hs[src] * dinv[dst]
        k_edge<<<(int)(((size_t)EL * 32 + TB - 1) / TB), TB>>>(hL, iL, Lsrc, Ldst, aL, EL);
        k_edge<<<(int)(((size_t)EG * 32 + TB - 1) / TB), TB>>>(hG, iG, Gsrc, Gdst, aG, EG);
        // LN + ReLU (+ residual from layer input for i>0)
        const float* res = (i > 0) ? xin : nullptr;
        k_ln<<<gbN32, TB>>>(aL, ln_g, ln_b, res, n);
        k_ln<<<gbN32, TB>>>(aG, ln_g, ln_b, res, n);
        // x_new = xG @ lwT + xL @ lwB + linb
        sgemm_k128<<<gbGem, 128>>>(aG, lwT, nullptr, nullptr, nullptr, xout, n);
        sgemm_k128<<<gbGem, 128>>>(aL, lwB, lbi, nullptr, xout, xout, n);

        xin  = xout;
        xout = (xout == xA) ? xB : xA;
    }

    // output layout from out_size: tuple (proj[N,64], x[N,128]) flattened in order
    size_t nP = (size_t)n * 64, nX = (size_t)n * 128;
    float* out = (float*)d_out;
    int do_proj = 1, do_copy = 0;
    float* xdst = nullptr;
    if ((size_t)out_size >= nP + nX)      { do_copy = 1; xdst = out + nP; }
    else if ((size_t)out_size == nX)      { do_proj = 0; do_copy = 1; xdst = out; }
    k_final<<<(n + 15) / 16, TB>>>(xin, finW, finb, out, xdst, n, do_proj, do_copy);
}